// round 6
// baseline (speedup 1.0000x reference)
// ExpertGather via legacy mma.sync tf32 (valid at PTX .target sm_100 — the harness
// compiles compute_100 PTX, so tcgen05/"a"-features are unavailable).
// y[b,e,k,j] = sum_i x[b, Ind[b,e,k], i] * W[e,i,j]
// x[8,2048,1024] f32, W[16,1024,1024] f32, Ind[8,16,256] int32 OR int64 (runtime-
// detected: tokens < 2048 so an int64 buffer's int32 view is (lo,0,lo,0,...)),
// y[8,16,256,1024] f32.
//
// CTA 128x128x32, 256 thr, 8 warps (2x4), warp tile 64x32, mma.m16n8k8.tf32.
// A (gathered rows) + B (W chunk) staged via cp.async, 2-stage pipeline.
// tf32 via explicit cvt.rna for round-to-nearest precision.

#include <cuda_runtime.h>
#include <cstdint>

#define DEVINL __device__ __forceinline__

DEVINL uint32_t smem_u32(const void* p) {
    uint32_t a;
    asm("{ .reg .u64 t; cvta.to.shared.u64 t, %1; cvt.u32.u64 %0, t; }" : "=r"(a) : "l"(p));
    return a;
}

DEVINL uint32_t f2tf32(float f) {
    uint32_t r;
    asm("cvt.rna.tf32.f32 %0, %1;" : "=r"(r) : "f"(f));
    return r;
}

#define CP_ASYNC16(dst, src) \
    asm volatile("cp.async.cg.shared.global [%0], [%1], 16;" :: "r"(dst), "l"(src))
#define CP_COMMIT()  asm volatile("cp.async.commit_group;" ::: "memory")
#define CP_WAIT1()   asm volatile("cp.async.wait_group 1;" ::: "memory")
#define CP_WAIT0()   asm volatile("cp.async.wait_group 0;" ::: "memory")

DEVINL void mma_tf32(float& d0, float& d1, float& d2, float& d3,
                     uint32_t a0, uint32_t a1, uint32_t a2, uint32_t a3,
                     uint32_t b0, uint32_t b1) {
    asm volatile("mma.sync.aligned.m16n8k8.row.col.f32.tf32.tf32.f32 "
                 "{%0,%1,%2,%3}, {%4,%5,%6,%7}, {%8,%9}, {%0,%1,%2,%3};"
                 : "+f"(d0), "+f"(d1), "+f"(d2), "+f"(d3)
                 : "r"(a0), "r"(a1), "r"(a2), "r"(a3), "r"(b0), "r"(b1));
}

// ---------------- problem constants ----------------
static constexpr int Bb = 8, Tt = 2048, IC = 1024, EE = 16, KG = 256, JD = 1024;
static constexpr int BM = 128, BN = 128, BK = 32;
static constexpr int CHUNKS = IC / BK;            // 32

// smem layout in floats
static constexpr int ASTR = 36;                   // 32 + 4 pad -> conflict-free frag loads
static constexpr int BSTR = 136;                  // 128 + 8 pad
static constexpr int TOK_OFF = 0;                 // 128 ints + 1 flag int (padded to 128+ ...)
static constexpr int FLAG_OFF = 130;              // detection flag slot
static constexpr int A_OFF   = 144;
static constexpr int ASZ     = BM * ASTR;         // 4608 floats / stage
static constexpr int B_OFF   = A_OFF + 2 * ASZ;   // 9360
static constexpr int BSZ     = BK * BSTR;         // 4352 floats / stage
static constexpr int SMEM_FLOATS = B_OFF + 2 * BSZ;   // -> ~72 KB
static constexpr uint32_t SMEM_BYTES = SMEM_FLOATS * 4;

__global__ void __launch_bounds__(256, 2)
eg_mma_kernel(const float* __restrict__ x, const float* __restrict__ W,
              const int* __restrict__ Ind, float* __restrict__ out) {
    extern __shared__ float sm[];
    int* tok  = reinterpret_cast<int*>(sm + TOK_OFF);
    int* flag = reinterpret_cast<int*>(sm + FLAG_OFF);

    const int tid = threadIdx.x, wid = tid >> 5, lid = tid & 31;
    const int pair = blockIdx.z;                  // b*16 + e
    const int b = pair >> 4, e = pair & 15;
    const int m0 = blockIdx.y * BM;
    const int n0 = blockIdx.x * BN;

    const float* xb = x + (size_t)b * Tt * IC;
    const float* We = W + (size_t)e * IC * JD + n0;

    // ---- dtype detection: int64 Ind (tokens<2048) viewed as int32 = (lo,0,lo,0,...) ----
    if (tid == 0) {
        int allz = 1;
        #pragma unroll
        for (int q = 0; q < 16; ++q) allz &= (Ind[2 * q + 1] == 0);
        flag[0] = allz;                            // 1 => int64 layout, stride 2
    }
    __syncthreads();
    const int stride = flag[0] ? 2 : 1;

    if (tid < BM) tok[tid] = Ind[(size_t)((size_t)pair * KG + m0 + tid) * stride];
    __syncthreads();

    // ---- per-thread cp.async source pointers / smem dst offsets ----
    const uint32_t sb = smem_u32(sm);

    // A: thread covers rows r_p = tid/8 + p*32, 16B slot j = tid%8
    const int aj = tid & 7;
    const float* aglob[4];
    uint32_t adst[4];
    #pragma unroll
    for (int p = 0; p < 4; ++p) {
        const int r = (tid >> 3) + p * 32;
        aglob[p] = xb + (size_t)tok[r] * IC + aj * 4;
        adst[p]  = sb + (uint32_t)(A_OFF + r * ASTR) * 4u + (uint32_t)aj * 16u;
    }
    // B: thread covers k rows k_q = tid/32 + q*8, 16B slot n4 = tid%32
    const int bn4 = tid & 31;
    const float* bglob[4];
    uint32_t bdst[4];
    #pragma unroll
    for (int q = 0; q < 4; ++q) {
        const int k = (tid >> 5) + q * 8;
        bglob[q] = We + (size_t)k * JD + bn4 * 4;
        bdst[q]  = sb + (uint32_t)(B_OFF + k * BSTR) * 4u + (uint32_t)bn4 * 16u;
    }

    auto load_stage = [&](int c, int s) {
        const uint32_t ao = (uint32_t)s * (ASZ * 4u);
        const uint32_t bo = (uint32_t)s * (BSZ * 4u);
        #pragma unroll
        for (int p = 0; p < 4; ++p)
            CP_ASYNC16(adst[p] + ao, aglob[p] + c * BK);
        #pragma unroll
        for (int q = 0; q < 4; ++q)
            CP_ASYNC16(bdst[q] + bo, bglob[q] + (size_t)c * BK * JD);
    };

    // ---- accumulators ----
    float d[4][4][4];
    #pragma unroll
    for (int i = 0; i < 4; ++i)
        #pragma unroll
        for (int f = 0; f < 4; ++f)
            #pragma unroll
            for (int v = 0; v < 4; ++v) d[i][f][v] = 0.0f;

    const int warp_m = wid >> 2, warp_n = wid & 3;   // 2 x 4 warp grid
    const int r0 = lid >> 2, c4 = lid & 3;

    load_stage(0, 0); CP_COMMIT();
    load_stage(1, 1); CP_COMMIT();

    for (int c = 0; c < CHUNKS; ++c) {
        if (c < CHUNKS - 2) CP_WAIT1(); else CP_WAIT0();
        __syncthreads();

        const float* As = sm + A_OFF + (c & 1) * ASZ + warp_m * 64 * ASTR;
        const float* Bs = sm + B_OFF + (c & 1) * BSZ + warp_n * 32;

        #pragma unroll
        for (int kk = 0; kk < 4; ++kk) {
            const int kc = kk * 8 + c4;
            uint32_t a[4][4], bb[4][2];
            #pragma unroll
            for (int i = 0; i < 4; ++i) {
                const float* ap = As + (i * 16 + r0) * ASTR + kc;
                a[i][0] = f2tf32(ap[0]);
                a[i][1] = f2tf32(ap[8 * ASTR]);
                a[i][2] = f2tf32(ap[4]);
                a[i][3] = f2tf32(ap[8 * ASTR + 4]);
            }
            #pragma unroll
            for (int f = 0; f < 4; ++f) {
                const float* bp = Bs + kc * BSTR + f * 8 + r0;
                bb[f][0] = f2tf32(bp[0]);
                bb[f][1] = f2tf32(bp[4 * BSTR]);
            }
            #pragma unroll
            for (int i = 0; i < 4; ++i)
                #pragma unroll
                for (int f = 0; f < 4; ++f)
                    mma_tf32(d[i][f][0], d[i][f][1], d[i][f][2], d[i][f][3],
                             a[i][0], a[i][1], a[i][2], a[i][3],
                             bb[f][0], bb[f][1]);
        }

        __syncthreads();
        if (c + 2 < CHUNKS) { load_stage(c + 2, c & 1); CP_COMMIT(); }
    }

    // ---- epilogue: d[i][f] -> y[pair, m0 + warp_m*64 + i*16 + {r0, r0+8}, n0 + ...] ----
    float* op = out + ((size_t)pair * KG + m0 + warp_m * 64) * JD + n0 + warp_n * 32;
    #pragma unroll
    for (int i = 0; i < 4; ++i) {
        #pragma unroll
        for (int f = 0; f < 4; ++f) {
            float* p0 = op + (size_t)(i * 16 + r0) * JD + f * 8 + 2 * c4;
            p0[0] = d[i][f][0];
            p0[1] = d[i][f][1];
            float* p1 = p0 + 8 * JD;
            p1[0] = d[i][f][2];
            p1[1] = d[i][f][3];
        }
    }
}

// ---------------- launch ----------------
extern "C" void kernel_launch(void* const* d_in, const int* in_sizes, int n_in,
                              void* d_out, int out_size) {
    const float* x   = (const float*)d_in[0];
    const float* W   = (const float*)d_in[1];
    const int*   Ind = (const int*)d_in[2];
    float*       y   = (float*)d_out;

    cudaFuncSetAttribute(eg_mma_kernel,
                         cudaFuncAttributeMaxDynamicSharedMemorySize, SMEM_BYTES);

    dim3 grid(JD / BN, KG / BM, Bb * EE);   // (8, 2, 128)
    eg_mma_kernel<<<grid, 256, SMEM_BYTES>>>(x, W, Ind, y);
}

// round 7
// speedup vs baseline: 1.0266x; 1.0266x over previous
// ExpertGather via legacy mma.sync tf32 (PTX .target sm_100 — no tcgen05).
// y[b,e,k,j] = sum_i x[b, Ind[b,e,k], i] * W[e,i,j]
// x[8,2048,1024] f32, W[16,1024,1024] f32, Ind int32-or-int64 (runtime-detected),
// y[8,16,256,1024] f32.
//
// R7: CTA 128x256x32, 8 warps (2x4), warp tile 64x64 -> aux:HMMA 2:1 (was 3:1).
// 3-stage cp.async pipeline (1 CTA/SM now), conflict-free padded smem,
// cvt.rna tf32 fragments. R6 baseline: 485.7us, tensor=50.5%, issue=41.6%.

#include <cuda_runtime.h>
#include <cstdint>

#define DEVINL __device__ __forceinline__

DEVINL uint32_t smem_u32(const void* p) {
    uint32_t a;
    asm("{ .reg .u64 t; cvta.to.shared.u64 t, %1; cvt.u32.u64 %0, t; }" : "=r"(a) : "l"(p));
    return a;
}

DEVINL uint32_t f2tf32(float f) {
    uint32_t r;
    asm("cvt.rna.tf32.f32 %0, %1;" : "=r"(r) : "f"(f));
    return r;
}

#define CP_ASYNC16(dst, src) \
    asm volatile("cp.async.cg.shared.global [%0], [%1], 16;" :: "r"(dst), "l"(src))
#define CP_COMMIT()  asm volatile("cp.async.commit_group;" ::: "memory")
#define CP_WAIT2()   asm volatile("cp.async.wait_group 2;" ::: "memory")
#define CP_WAIT1()   asm volatile("cp.async.wait_group 1;" ::: "memory")
#define CP_WAIT0()   asm volatile("cp.async.wait_group 0;" ::: "memory")

DEVINL void mma_tf32(float& d0, float& d1, float& d2, float& d3,
                     uint32_t a0, uint32_t a1, uint32_t a2, uint32_t a3,
                     uint32_t b0, uint32_t b1) {
    asm volatile("mma.sync.aligned.m16n8k8.row.col.f32.tf32.tf32.f32 "
                 "{%0,%1,%2,%3}, {%4,%5,%6,%7}, {%8,%9}, {%0,%1,%2,%3};"
                 : "+f"(d0), "+f"(d1), "+f"(d2), "+f"(d3)
                 : "r"(a0), "r"(a1), "r"(a2), "r"(a3), "r"(b0), "r"(b1));
}

// ---------------- problem constants ----------------
static constexpr int Bb = 8, Tt = 2048, IC = 1024, EE = 16, KG = 256, JD = 1024;
static constexpr int BM = 128, BN = 256, BK = 32;
static constexpr int CHUNKS = IC / BK;            // 32
static constexpr int STAGES = 3;

// smem layout in floats
static constexpr int ASTR = 36;                   // 32 + 4 pad
static constexpr int BSTR = 264;                  // 256 + 8 pad
static constexpr int TOK_OFF  = 0;                // 128 ints
static constexpr int FLAG_OFF = 130;
static constexpr int A_OFF    = 144;
static constexpr int ASZ      = BM * ASTR;        // 4608 floats / stage
static constexpr int B_OFF    = A_OFF + STAGES * ASZ;   // 13968
static constexpr int BSZ      = BK * BSTR;        // 8448 floats / stage
static constexpr int SMEM_FLOATS = B_OFF + STAGES * BSZ;   // 39312 -> 157248 B
static constexpr uint32_t SMEM_BYTES = SMEM_FLOATS * 4;

__global__ void __launch_bounds__(256, 1)
eg_mma_kernel(const float* __restrict__ x, const float* __restrict__ W,
              const int* __restrict__ Ind, float* __restrict__ out) {
    extern __shared__ float sm[];
    int* tok  = reinterpret_cast<int*>(sm + TOK_OFF);
    int* flag = reinterpret_cast<int*>(sm + FLAG_OFF);

    const int tid = threadIdx.x, wid = tid >> 5, lid = tid & 31;
    const int pair = blockIdx.z;                  // b*16 + e
    const int b = pair >> 4, e = pair & 15;
    const int m0 = blockIdx.y * BM;
    const int n0 = blockIdx.x * BN;

    const float* xb = x + (size_t)b * Tt * IC;
    const float* We = W + (size_t)e * IC * JD + n0;

    // ---- dtype detection: int64 Ind (tokens<2048) viewed as int32 = (lo,0,lo,0,...) ----
    if (tid == 0) {
        int allz = 1;
        #pragma unroll
        for (int q = 0; q < 16; ++q) allz &= (Ind[2 * q + 1] == 0);
        flag[0] = allz;                            // 1 => int64 layout, stride 2
    }
    __syncthreads();
    const int stride = flag[0] ? 2 : 1;

    if (tid < BM) tok[tid] = Ind[(size_t)((size_t)pair * KG + m0 + tid) * stride];
    __syncthreads();

    // ---- per-thread staging pointers ----
    const uint32_t sb = smem_u32(sm);

    // A: rows r_p = tid/8 + p*32, 16B slot aj = tid%8
    const int aj = tid & 7;
    const float* aglob[4];
    uint32_t adst[4];
    #pragma unroll
    for (int p = 0; p < 4; ++p) {
        const int r = (tid >> 3) + p * 32;
        aglob[p] = xb + (size_t)tok[r] * IC + aj * 4;
        adst[p]  = sb + (uint32_t)(A_OFF + r * ASTR) * 4u + (uint32_t)aj * 16u;
    }
    // B: 16B slot bn4 = tid%64 (n = bn4*4), k rows = tid/64 + q*4, q=0..7
    const int bn4 = tid & 63;
    const int kb  = tid >> 6;                      // 0..3
    const float* bglob = We + (size_t)kb * JD + bn4 * 4;
    const uint32_t bdst0 = sb + (uint32_t)(B_OFF + kb * BSTR) * 4u + (uint32_t)bn4 * 16u;

    auto load_stage = [&](int c, int s) {
        const uint32_t ao = (uint32_t)s * (ASZ * 4u);
        const uint32_t bo = (uint32_t)s * (BSZ * 4u);
        #pragma unroll
        for (int p = 0; p < 4; ++p)
            CP_ASYNC16(adst[p] + ao, aglob[p] + c * BK);
        const float* bsrc = bglob + (size_t)c * BK * JD;
        #pragma unroll
        for (int q = 0; q < 8; ++q)
            CP_ASYNC16(bdst0 + bo + (uint32_t)q * (4u * BSTR * 4u),
                       bsrc + (size_t)q * 4 * JD);
    };

    // ---- accumulators: 4 (i: m) x 8 (f: n) x 4 ----
    float d[4][8][4];
    #pragma unroll
    for (int i = 0; i < 4; ++i)
        #pragma unroll
        for (int f = 0; f < 8; ++f)
            #pragma unroll
            for (int v = 0; v < 4; ++v) d[i][f][v] = 0.0f;

    const int warp_m = wid >> 2, warp_n = wid & 3;   // 2 x 4 warp grid, 64x64 tiles
    const int r0 = lid >> 2, c4 = lid & 3;

    load_stage(0, 0); CP_COMMIT();
    load_stage(1, 1); CP_COMMIT();
    load_stage(2, 2); CP_COMMIT();

    int s = 0;                                     // stage = c % 3
    for (int c = 0; c < CHUNKS; ++c) {
        if (c <= CHUNKS - 3)      CP_WAIT2();
        else if (c == CHUNKS - 2) CP_WAIT1();
        else                      CP_WAIT0();
        __syncthreads();

        const float* As = sm + A_OFF + s * ASZ + warp_m * 64 * ASTR;
        const float* Bs = sm + B_OFF + s * BSZ + warp_n * 64;

        #pragma unroll
        for (int kk = 0; kk < 4; ++kk) {
            const int kc = kk * 8 + c4;
            uint32_t a[4][4], bb[8][2];
            #pragma unroll
            for (int i = 0; i < 4; ++i) {
                const float* ap = As + (i * 16 + r0) * ASTR + kc;
                a[i][0] = f2tf32(ap[0]);
                a[i][1] = f2tf32(ap[8 * ASTR]);
                a[i][2] = f2tf32(ap[4]);
                a[i][3] = f2tf32(ap[8 * ASTR + 4]);
            }
            #pragma unroll
            for (int f = 0; f < 8; ++f) {
                const float* bp = Bs + kc * BSTR + f * 8 + r0;
                bb[f][0] = f2tf32(bp[0]);
                bb[f][1] = f2tf32(bp[4 * BSTR]);
            }
            #pragma unroll
            for (int i = 0; i < 4; ++i)
                #pragma unroll
                for (int f = 0; f < 8; ++f)
                    mma_tf32(d[i][f][0], d[i][f][1], d[i][f][2], d[i][f][3],
                             a[i][0], a[i][1], a[i][2], a[i][3],
                             bb[f][0], bb[f][1]);
        }

        __syncthreads();
        if (c + STAGES < CHUNKS) { load_stage(c + STAGES, s); CP_COMMIT(); }
        s = (s == 2) ? 0 : s + 1;
    }

    // ---- epilogue ----
    float* op = out + ((size_t)pair * KG + m0 + warp_m * 64) * JD + n0 + warp_n * 64;
    #pragma unroll
    for (int i = 0; i < 4; ++i) {
        #pragma unroll
        for (int f = 0; f < 8; ++f) {
            float* p0 = op + (size_t)(i * 16 + r0) * JD + f * 8 + 2 * c4;
            p0[0] = d[i][f][0];
            p0[1] = d[i][f][1];
            float* p1 = p0 + 8 * JD;
            p1[0] = d[i][f][2];
            p1[1] = d[i][f][3];
        }
    }
}

// ---------------- launch ----------------
extern "C" void kernel_launch(void* const* d_in, const int* in_sizes, int n_in,
                              void* d_out, int out_size) {
    const float* x   = (const float*)d_in[0];
    const float* W   = (const float*)d_in[1];
    const int*   Ind = (const int*)d_in[2];
    float*       y   = (float*)d_out;

    cudaFuncSetAttribute(eg_mma_kernel,
                         cudaFuncAttributeMaxDynamicSharedMemorySize, SMEM_BYTES);

    dim3 grid(JD / BN, KG / BM, Bb * EE);   // (4, 2, 128)
    eg_mma_kernel<<<grid, 256, SMEM_BYTES>>>(x, W, Ind, y);
}